// round 13
// baseline (speedup 1.0000x reference)
#include <cuda_runtime.h>

typedef unsigned long long u64;

// ---- packed f32x2 helpers (Blackwell; ptxas won't auto-fuse) ----
static __device__ __forceinline__ u64 pack2(float v) {
    u64 r; asm("mov.b64 %0, {%1, %1};" : "=l"(r) : "f"(v)); return r;
}
static __device__ __forceinline__ u64 mul2(u64 a, u64 b) {
    u64 r; asm("mul.rn.f32x2 %0, %1, %2;" : "=l"(r) : "l"(a), "l"(b)); return r;
}
static __device__ __forceinline__ u64 fma2(u64 a, u64 b, u64 c) {
    u64 r; asm("fma.rn.f32x2 %0, %1, %2, %3;" : "=l"(r) : "l"(a), "l"(b), "l"(c)); return r;
}
struct P4 { u64 a, b; };

// One 128-bit non-coherent load per corner: minimum L1 wavefronts.
static __device__ __forceinline__ P4 ld4v(const float4* __restrict__ p) {
    P4 r;
    asm("ld.global.nc.v2.u64 {%0, %1}, [%2];" : "=l"(r.a), "=l"(r.b) : "l"(p));
    return r;
}
static __device__ __forceinline__ P4 lerp4p(P4 A, P4 B, u64 WA, u64 WB) {
    P4 r;
    r.a = fma2(A.a, WA, mul2(B.a, WB));
    r.b = fma2(A.b, WA, mul2(B.b, WB));
    return r;
}

// streaming stores (evict-first): keep output from evicting features in L2
static __device__ __forceinline__ void st128cs(float* p, u64 a, u64 b) {
    asm volatile("st.global.cs.v2.u64 [%0], {%1, %2};" :: "l"(p), "l"(a), "l"(b));
}
static __device__ __forceinline__ void st128cs_f(float* p, float a, float b, float c, float d) {
    u64 lo, hi;
    asm("mov.b64 %0, {%1, %2};" : "=l"(lo) : "f"(a), "f"(b));
    asm("mov.b64 %0, {%1, %2};" : "=l"(hi) : "f"(c), "f"(d));
    st128cs(p, lo, hi);
}
static __device__ __forceinline__ void st32cs(float* p, float a) {
    asm volatile("st.global.cs.f32 [%0], %1;" :: "l"(p), "f"(a));
}
static __device__ __forceinline__ float shdn(float v) {
    return __shfl_down_sync(0xffffffffu, v, 1);
}

// Multi-res trilinear sampling. Levels 1 (64^3x32), 2 (32^3x64), 3 (16^3x128).
// Out per point: [32 | 64 | 128 | mesh 3] = 227 floats.
// 64 threads/point, 4 channels/thread (R10 mapping):
//   slot 0..7 -> lev1, 8..23 -> lev2, 24..55 -> lev3, 56..58 -> mesh, 59..63 idle.
// Misaligned output rows (obase%4 != 0) are realigned in-register via
// __shfl_down so every store is an aligned STG.128 (plus <=3 edge words).
__global__ void __launch_bounds__(256, 8) trilerp_kernel(
    const float* __restrict__ f1, const float* __restrict__ f2, const float* __restrict__ f3,
    const float* __restrict__ coords, const float* __restrict__ meshf,
    float* __restrict__ out, int Npts)
{
    int t = blockIdx.x * 256 + threadIdx.x;
    int pInB = t >> 6;
    if (pInB >= Npts) return;
    int slot = t & 63;
    int b = blockIdx.y;
    int point = b * Npts + pInB;
    size_t obase = (size_t)point * 227;

    bool active = (slot < 56);

    // mesh passthrough early (overlaps everything below)
    if (slot >= 56 && slot < 59)
        st32cs(out + obase + 224 + (slot - 56), __ldg(meshf + point * 3 + (slot - 56)));

    float cx = __ldg(coords + point * 3 + 0);
    float cy = __ldg(coords + point * 3 + 1);
    float cz = __ldg(coords + point * 3 + 2);

    int lev = (slot < 8) ? 1 : ((slot < 24) ? 2 : 3);
    const float4* __restrict__ fp =
        (const float4*)((lev == 1) ? f1 : ((lev == 2) ? f2 : f3));
    int cstart = (lev == 1) ? 0 : ((lev == 2) ? 8 : 24);
    int R  = 128 >> lev;         // 64 / 32 / 16
    int s4 = 4 << lev;           // C/4 = 8 / 16 / 32
    int c4 = active ? (slot - cstart) : 0;  // clamp idle lanes in-bounds (shared line)

    float scale = (float)R;
    float hi = scale - 1.01f;
    float ix = fminf(fmaxf(cx * scale, 0.01f), hi);
    float iy = fminf(fmaxf(cy * scale, 0.01f), hi);
    float iz = fminf(fmaxf(cz * scale, 0.01f), hi);

    float fx1 = floorf(ix), fx2 = ceilf(ix);
    float fy1 = floorf(iy), fy2 = ceilf(iy);
    float fz1 = floorf(iz), fz2 = ceilf(iz);

    u64 WX = pack2(ix - fx1), WX2 = pack2(fx2 - ix);
    u64 WY = pack2(iy - fy1), WY2 = pack2(fy2 - iy);
    u64 WZ = pack2(iz - fz1), WZ2 = pack2(fz2 - iz);

    int x1 = (int)fx1, y1 = (int)fy1, z1 = (int)fz1;
    int dxs = ((int)fx2 - x1) * R * R * s4;
    int dys = ((int)fy2 - y1) * R * s4;
    int dzs = ((int)fz2 - z1) * s4;
    const float4* p = fp + (((b * R + x1) * R + y1) * R + z1) * s4 + c4;

    // 8 independent LDG.128s (front-batched; wavefronts = lines = floor)
    P4 v111 = ld4v(p);
    P4 v211 = ld4v(p + dxs);
    P4 v121 = ld4v(p + dys);
    P4 v221 = ld4v(p + dxs + dys);
    P4 v112 = ld4v(p + dzs);
    P4 v212 = ld4v(p + dxs + dzs);
    P4 v122 = ld4v(p + dys + dzs);
    P4 v222 = ld4v(p + dxs + dys + dzs);

    P4 la = lerp4p(v211, v111, WX, WX2);
    P4 lb = lerp4p(v221, v121, WX, WX2);
    P4 l1 = lerp4p(lb, la, WY, WY2);
    P4 lc = lerp4p(v212, v112, WX, WX2);
    P4 ld_ = lerp4p(v222, v122, WX, WX2);
    P4 l2 = lerp4p(ld_, lc, WY, WY2);
    P4 r  = lerp4p(l2, l1, WZ, WZ2);

    // ---- stores ----
    unsigned m = (unsigned)(obase & 3);      // warp-uniform (one point per 2 warps)
    int slot0 = slot & 32;                   // warp chunk start (0 or 32)
    int li = slot - slot0;                   // lane index within chunk
    int n = slot0 ? 24 : 32;                 // active lanes in this warp's chunk
    float* qb = out + obase + 4 * slot0;     // warp chunk word base

    if (m == 0) {
        if (active) st128cs(qb + 4 * li, r.a, r.b);
        return;
    }

    // realign: lane i writes aligned chunk = last m words of self + first 4-m of lane i+1
    float w0, w1, w2, w3;
    asm("mov.b64 {%0, %1}, %2;" : "=f"(w0), "=f"(w1) : "l"(r.a));
    asm("mov.b64 {%0, %1}, %2;" : "=f"(w2), "=f"(w3) : "l"(r.b));
    float* A = qb + (4 - m);                 // aligned base (obase+4-m ≡ 0 mod 4)
    bool interior = active && (li < n - 1);
    bool head = (li == 0);                   // slot 0 / 32, always active
    bool tail = (li == n - 1);               // slot 31 / 55, always active

    if (m == 1) {
        float n0 = shdn(w0), n1 = shdn(w1), n2 = shdn(w2);
        if (interior) st128cs_f(A + 4 * li, w3, n0, n1, n2);
        if (head) { st32cs(qb + 0, w0); st32cs(qb + 1, w1); st32cs(qb + 2, w2); }
        if (tail) { st32cs(qb + 4 * n - 1, w3); }
    } else if (m == 2) {
        float n0 = shdn(w0), n1 = shdn(w1);
        if (interior) st128cs_f(A + 4 * li, w2, w3, n0, n1);
        if (head) { st32cs(qb + 0, w0); st32cs(qb + 1, w1); }
        if (tail) { st32cs(qb + 4 * n - 2, w2); st32cs(qb + 4 * n - 1, w3); }
    } else {
        float n0 = shdn(w0);
        if (interior) st128cs_f(A + 4 * li, w1, w2, w3, n0);
        if (head) { st32cs(qb + 0, w0); }
        if (tail) { st32cs(qb + 4 * n - 3, w1); st32cs(qb + 4 * n - 2, w2);
                    st32cs(qb + 4 * n - 1, w3); }
    }
}

extern "C" void kernel_launch(void* const* d_in, const int* in_sizes, int n_in,
                              void* d_out, int out_size)
{
    // metadata order: features0..features4, mesh_coords, mesh_features
    const float* f1     = (const float*)d_in[1];
    const float* f2     = (const float*)d_in[2];
    const float* f3     = (const float*)d_in[3];
    const float* coords = (const float*)d_in[5];
    const float* meshf  = (const float*)d_in[6];
    float* out = (float*)d_out;

    int B    = in_sizes[1] / (64 * 64 * 64 * 32);
    int BN   = in_sizes[5] / 3;
    int Npts = BN / B;

    long long tpb = (long long)Npts * 64;
    dim3 grid((unsigned)((tpb + 255) / 256), (unsigned)B);
    trilerp_kernel<<<grid, 256>>>(f1, f2, f3, coords, meshf, out, Npts);
}

// round 14
// speedup vs baseline: 1.2077x; 1.2077x over previous
#include <cuda_runtime.h>

typedef unsigned long long u64;

// ---- packed f32x2 helpers (Blackwell; ptxas won't auto-fuse) ----
static __device__ __forceinline__ u64 pack2(float v) {
    u64 r; asm("mov.b64 %0, {%1, %1};" : "=l"(r) : "f"(v)); return r;
}
static __device__ __forceinline__ u64 mul2(u64 a, u64 b) {
    u64 r; asm("mul.rn.f32x2 %0, %1, %2;" : "=l"(r) : "l"(a), "l"(b)); return r;
}
static __device__ __forceinline__ u64 fma2(u64 a, u64 b, u64 c) {
    u64 r; asm("fma.rn.f32x2 %0, %1, %2, %3;" : "=l"(r) : "l"(a), "l"(b), "l"(c)); return r;
}
struct P4 { u64 a, b; };

// One 128-bit non-coherent load per corner: minimum L1 wavefronts.
static __device__ __forceinline__ P4 ld4v(const float4* __restrict__ p) {
    P4 r;
    asm("ld.global.nc.v2.u64 {%0, %1}, [%2];" : "=l"(r.a), "=l"(r.b) : "l"(p));
    return r;
}
// Same, with L2 256B prefetch hint: pre-stages the adjacent z2 row
// (128B/256B away at lev1/lev2) for the DRAM-miss fraction. Never wasted —
// the partner line is always consumed by the z2-plane load.
static __device__ __forceinline__ P4 ld4v_pf(const float4* __restrict__ p) {
    P4 r;
    asm("ld.global.nc.L2::256B.v2.u64 {%0, %1}, [%2];" : "=l"(r.a), "=l"(r.b) : "l"(p));
    return r;
}
static __device__ __forceinline__ P4 lerp4p(P4 A, P4 B, u64 WA, u64 WB) {
    P4 r;
    r.a = fma2(A.a, WA, mul2(B.a, WB));
    r.b = fma2(A.b, WA, mul2(B.b, WB));
    return r;
}

// streaming stores (evict-first): keep the 91MB output from evicting the
// ~78MB feature working set out of L2
static __device__ __forceinline__ void st128cs(float* p, u64 a, u64 b) {
    asm volatile("st.global.cs.v2.u64 [%0], {%1, %2};" :: "l"(p), "l"(a), "l"(b));
}
static __device__ __forceinline__ void st64cs(float* p, u64 a) {
    asm volatile("st.global.cs.u64 [%0], %1;" :: "l"(p), "l"(a));
}
static __device__ __forceinline__ void st32cs(float* p, float a) {
    asm volatile("st.global.cs.f32 [%0], %1;" :: "l"(p), "f"(a));
}

// Multi-res trilinear sampling. Levels 1 (64^3x32), 2 (32^3x64), 3 (16^3x128).
// Out per point: [32 | 64 | 128 | mesh 3] = 227 floats.
// 64 threads/point, 4 channels/thread:
//   slot 0..7 -> lev1, 8..23 -> lev2, 24..55 -> lev3, 56..58 -> mesh.
// Global out channel = 4*slot for slots 0..55 (concat offsets align).
// __launch_bounds__(256, 8) forces <=32 regs -> 8 blocks (64 warps)/SM resident.
__global__ void __launch_bounds__(256, 8) trilerp_kernel(
    const float* __restrict__ f1, const float* __restrict__ f2, const float* __restrict__ f3,
    const float* __restrict__ coords, const float* __restrict__ meshf,
    float* __restrict__ out, int Npts)
{
    int t = blockIdx.x * 256 + threadIdx.x;
    int pInB = t >> 6;
    if (pInB >= Npts) return;
    int slot = t & 63;
    int b = blockIdx.y;
    int point = b * Npts + pInB;
    size_t obase = (size_t)point * 227;

    if (slot >= 56) {
        int k = slot - 56;
        if (k < 3) st32cs(out + obase + 224 + k, __ldg(meshf + point * 3 + k));
        return;
    }

    float cx = __ldg(coords + point * 3 + 0);
    float cy = __ldg(coords + point * 3 + 1);
    float cz = __ldg(coords + point * 3 + 2);

    int lev = (slot < 8) ? 1 : ((slot < 24) ? 2 : 3);
    const float4* __restrict__ fp =
        (const float4*)((lev == 1) ? f1 : ((lev == 2) ? f2 : f3));
    int cstart = (lev == 1) ? 0 : ((lev == 2) ? 8 : 24);
    int R  = 128 >> lev;         // 64 / 32 / 16
    int s4 = 4 << lev;           // C/4 = 8 / 16 / 32
    int c4 = slot - cstart;      // channel base in float4 units

    float scale = (float)R;      // 0.5^lev * 128 == R
    float hi = scale - 1.01f;
    float ix = fminf(fmaxf(cx * scale, 0.01f), hi);
    float iy = fminf(fmaxf(cy * scale, 0.01f), hi);
    float iz = fminf(fmaxf(cz * scale, 0.01f), hi);

    float fx1 = floorf(ix), fx2 = ceilf(ix);
    float fy1 = floorf(iy), fy2 = ceilf(iy);
    float fz1 = floorf(iz), fz2 = ceilf(iz);

    u64 WX = pack2(ix - fx1), WX2 = pack2(fx2 - ix);
    u64 WY = pack2(iy - fy1), WY2 = pack2(fy2 - iy);
    u64 WZ = pack2(iz - fz1), WZ2 = pack2(fz2 - iz);

    int x1 = (int)fx1, y1 = (int)fy1, z1 = (int)fz1;
    // corner step offsets (0 or one full stride) in float4 units
    int dxs = ((int)fx2 - x1) * R * R * s4;
    int dys = ((int)fy2 - y1) * R * s4;
    int dzs = ((int)fz2 - z1) * s4;
    const float4* p = fp + (((b * R + x1) * R + y1) * R + z1) * s4 + c4;

    // 8 independent LDG.128s (front-batched; wavefronts = lines = floor).
    // z1-plane loads carry the L2::256B hint to pre-stage the z2 rows.
    P4 v111 = ld4v_pf(p);
    P4 v211 = ld4v_pf(p + dxs);
    P4 v121 = ld4v_pf(p + dys);
    P4 v221 = ld4v_pf(p + dxs + dys);
    P4 v112 = ld4v(p + dzs);
    P4 v212 = ld4v(p + dxs + dzs);
    P4 v122 = ld4v(p + dys + dzs);
    P4 v222 = ld4v(p + dxs + dys + dzs);

    // z = z1 plane
    P4 la = lerp4p(v211, v111, WX, WX2);
    P4 lb = lerp4p(v221, v121, WX, WX2);
    P4 l1 = lerp4p(lb, la, WY, WY2);
    // z = z2 plane
    P4 lc = lerp4p(v212, v112, WX, WX2);
    P4 ld_ = lerp4p(v222, v122, WX, WX2);
    P4 l2 = lerp4p(ld_, lc, WY, WY2);

    P4 r = lerp4p(l2, l1, WZ, WZ2);

    // out alignment class is warp-uniform (4*slot ≡ 0 mod 4; obase mod 4 fixed per point)
    unsigned omod = (unsigned)(obase & 3);
    float* q = out + obase + 4 * slot;
    if (omod == 0) {
        st128cs(q, r.a, r.b);                 // STG.128
    } else if ((omod & 1) == 0) {
        st64cs(q, r.a);                       // 2x STG.64
        st64cs(q + 2, r.b);
    } else {
        // q odd -> q+1 is 8B-aligned: STG.32 + STG.64 + STG.32
        float a0, a1, b0, b1;
        asm("mov.b64 {%0,%1}, %2;" : "=f"(a0), "=f"(a1) : "l"(r.a));
        asm("mov.b64 {%0,%1}, %2;" : "=f"(b0), "=f"(b1) : "l"(r.b));
        u64 mid;
        asm("mov.b64 %0, {%1, %2};" : "=l"(mid) : "f"(a1), "f"(b0));
        st32cs(q + 0, a0);
        st64cs(q + 1, mid);
        st32cs(q + 3, b1);
    }
}

extern "C" void kernel_launch(void* const* d_in, const int* in_sizes, int n_in,
                              void* d_out, int out_size)
{
    // metadata order: features0..features4, mesh_coords, mesh_features
    const float* f1     = (const float*)d_in[1];
    const float* f2     = (const float*)d_in[2];
    const float* f3     = (const float*)d_in[3];
    const float* coords = (const float*)d_in[5];
    const float* meshf  = (const float*)d_in[6];
    float* out = (float*)d_out;

    int B    = in_sizes[1] / (64 * 64 * 64 * 32);
    int BN   = in_sizes[5] / 3;
    int Npts = BN / B;

    long long tpb = (long long)Npts * 64;
    dim3 grid((unsigned)((tpb + 255) / 256), (unsigned)B);
    trilerp_kernel<<<grid, 256>>>(f1, f2, f3, coords, meshf, out, Npts);
}

// round 15
// speedup vs baseline: 1.2970x; 1.0739x over previous
#include <cuda_runtime.h>

typedef unsigned long long u64;

// ---- packed f32x2 helpers (Blackwell; ptxas won't auto-fuse) ----
static __device__ __forceinline__ u64 pack2(float v) {
    u64 r; asm("mov.b64 %0, {%1, %1};" : "=l"(r) : "f"(v)); return r;
}
static __device__ __forceinline__ u64 mul2(u64 a, u64 b) {
    u64 r; asm("mul.rn.f32x2 %0, %1, %2;" : "=l"(r) : "l"(a), "l"(b)); return r;
}
static __device__ __forceinline__ u64 fma2(u64 a, u64 b, u64 c) {
    u64 r; asm("fma.rn.f32x2 %0, %1, %2, %3;" : "=l"(r) : "l"(a), "l"(b), "l"(c)); return r;
}
struct P4 { u64 a, b; };

// One 128-bit non-coherent load per corner: minimum L1 wavefronts.
static __device__ __forceinline__ P4 ld4v(const float4* __restrict__ p) {
    P4 r;
    asm("ld.global.nc.v2.u64 {%0, %1}, [%2];" : "=l"(r.a), "=l"(r.b) : "l"(p));
    return r;
}
// z1-plane loads: L2 256B prefetch hint pre-stages the adjacent z2 row.
static __device__ __forceinline__ P4 ld4v_pf(const float4* __restrict__ p) {
    P4 r;
    asm("ld.global.nc.L2::256B.v2.u64 {%0, %1}, [%2];" : "=l"(r.a), "=l"(r.b) : "l"(p));
    return r;
}
static __device__ __forceinline__ P4 lerp4p(P4 A, P4 B, u64 WA, u64 WB) {
    P4 r;
    r.a = fma2(A.a, WA, mul2(B.a, WB));
    r.b = fma2(A.b, WA, mul2(B.b, WB));
    return r;
}

// streaming stores (evict-first): keep the 91MB output from evicting the
// ~78MB feature working set out of L2
static __device__ __forceinline__ void st128cs(float* p, u64 a, u64 b) {
    asm volatile("st.global.cs.v2.u64 [%0], {%1, %2};" :: "l"(p), "l"(a), "l"(b));
}
static __device__ __forceinline__ void st64cs(float* p, u64 a) {
    asm volatile("st.global.cs.u64 [%0], %1;" :: "l"(p), "l"(a));
}
static __device__ __forceinline__ void st32cs(float* p, float a) {
    asm volatile("st.global.cs.f32 [%0], %1;" :: "l"(p), "f"(a));
}

// Multi-res trilinear sampling. Levels 1 (64^3x32), 2 (32^3x64), 3 (16^3x128).
// Out per point: [32 | 64 | 128 | mesh 3] = 227 floats.
// 64 threads/point, 4 channels/thread:
//   slot 0..7 -> lev1, 8..23 -> lev2, 24..55 -> lev3, 56..58 -> mesh.
// Block = 128 threads = 2 points. __launch_bounds__(128, 16): 32 regs,
// 16 CTAs x 4 warps = 64 warps/SM resident with half-size scheduling
// granularity (smooths cross-CTA L1tex-queue completion spread).
__global__ void __launch_bounds__(128, 16) trilerp_kernel(
    const float* __restrict__ f1, const float* __restrict__ f2, const float* __restrict__ f3,
    const float* __restrict__ coords, const float* __restrict__ meshf,
    float* __restrict__ out, int Npts)
{
    int t = blockIdx.x * 128 + threadIdx.x;
    int pInB = t >> 6;
    if (pInB >= Npts) return;
    int slot = t & 63;
    int b = blockIdx.y;
    int point = b * Npts + pInB;
    size_t obase = (size_t)point * 227;

    if (slot >= 56) {
        int k = slot - 56;
        if (k < 3) st32cs(out + obase + 224 + k, __ldg(meshf + point * 3 + k));
        return;
    }

    float cx = __ldg(coords + point * 3 + 0);
    float cy = __ldg(coords + point * 3 + 1);
    float cz = __ldg(coords + point * 3 + 2);

    int lev = (slot < 8) ? 1 : ((slot < 24) ? 2 : 3);
    const float4* __restrict__ fp =
        (const float4*)((lev == 1) ? f1 : ((lev == 2) ? f2 : f3));
    int cstart = (lev == 1) ? 0 : ((lev == 2) ? 8 : 24);
    int R  = 128 >> lev;         // 64 / 32 / 16
    int s4 = 4 << lev;           // C/4 = 8 / 16 / 32
    int c4 = slot - cstart;      // channel base in float4 units

    float scale = (float)R;      // 0.5^lev * 128 == R
    float hi = scale - 1.01f;
    float ix = fminf(fmaxf(cx * scale, 0.01f), hi);
    float iy = fminf(fmaxf(cy * scale, 0.01f), hi);
    float iz = fminf(fmaxf(cz * scale, 0.01f), hi);

    float fx1 = floorf(ix), fx2 = ceilf(ix);
    float fy1 = floorf(iy), fy2 = ceilf(iy);
    float fz1 = floorf(iz), fz2 = ceilf(iz);

    u64 WX = pack2(ix - fx1), WX2 = pack2(fx2 - ix);
    u64 WY = pack2(iy - fy1), WY2 = pack2(fy2 - iy);
    u64 WZ = pack2(iz - fz1), WZ2 = pack2(fz2 - iz);

    int x1 = (int)fx1, y1 = (int)fy1, z1 = (int)fz1;
    // corner step offsets (0 or one full stride) in float4 units
    int dxs = ((int)fx2 - x1) * R * R * s4;
    int dys = ((int)fy2 - y1) * R * s4;
    int dzs = ((int)fz2 - z1) * s4;
    const float4* p = fp + (((b * R + x1) * R + y1) * R + z1) * s4 + c4;

    // 8 independent LDG.128s (front-batched; wavefronts = lines = floor)
    P4 v111 = ld4v_pf(p);
    P4 v211 = ld4v_pf(p + dxs);
    P4 v121 = ld4v_pf(p + dys);
    P4 v221 = ld4v_pf(p + dxs + dys);
    P4 v112 = ld4v(p + dzs);
    P4 v212 = ld4v(p + dxs + dzs);
    P4 v122 = ld4v(p + dys + dzs);
    P4 v222 = ld4v(p + dxs + dys + dzs);

    // z = z1 plane
    P4 la = lerp4p(v211, v111, WX, WX2);
    P4 lb = lerp4p(v221, v121, WX, WX2);
    P4 l1 = lerp4p(lb, la, WY, WY2);
    // z = z2 plane
    P4 lc = lerp4p(v212, v112, WX, WX2);
    P4 ld_ = lerp4p(v222, v122, WX, WX2);
    P4 l2 = lerp4p(ld_, lc, WY, WY2);

    P4 r = lerp4p(l2, l1, WZ, WZ2);

    // out alignment class is warp-uniform (4*slot ≡ 0 mod 4; obase mod 4 fixed per point)
    unsigned omod = (unsigned)(obase & 3);
    float* q = out + obase + 4 * slot;
    if (omod == 0) {
        st128cs(q, r.a, r.b);                 // STG.128
    } else if ((omod & 1) == 0) {
        st64cs(q, r.a);                       // 2x STG.64
        st64cs(q + 2, r.b);
    } else {
        // q odd -> q+1 is 8B-aligned: STG.32 + STG.64 + STG.32
        float a0, a1, b0, b1;
        asm("mov.b64 {%0,%1}, %2;" : "=f"(a0), "=f"(a1) : "l"(r.a));
        asm("mov.b64 {%0,%1}, %2;" : "=f"(b0), "=f"(b1) : "l"(r.b));
        u64 mid;
        asm("mov.b64 %0, {%1, %2};" : "=l"(mid) : "f"(a1), "f"(b0));
        st32cs(q + 0, a0);
        st64cs(q + 1, mid);
        st32cs(q + 3, b1);
    }
}

extern "C" void kernel_launch(void* const* d_in, const int* in_sizes, int n_in,
                              void* d_out, int out_size)
{
    // metadata order: features0..features4, mesh_coords, mesh_features
    const float* f1     = (const float*)d_in[1];
    const float* f2     = (const float*)d_in[2];
    const float* f3     = (const float*)d_in[3];
    const float* coords = (const float*)d_in[5];
    const float* meshf  = (const float*)d_in[6];
    float* out = (float*)d_out;

    int B    = in_sizes[1] / (64 * 64 * 64 * 32);
    int BN   = in_sizes[5] / 3;
    int Npts = BN / B;

    long long tpb = (long long)Npts * 64;
    dim3 grid((unsigned)((tpb + 127) / 128), (unsigned)B);
    trilerp_kernel<<<grid, 128>>>(f1, f2, f3, coords, meshf, out, Npts);
}